// round 6
// baseline (speedup 1.0000x reference)
#include <cuda_runtime.h>
#include <cuda_bf16.h>
#include <cstdint>

// ---------------------------------------------------------------------------
// WaveNet vocoder via mma.sync bf16 (hi/lo split, 3 passes) — sm_103-safe PTX.
// R6: 128(M)x256(N) CTA tiles, R3-proven SROW=144 smem layout + 2-stage
// cp.async ping-pong. Launch order tuned so ncu -s5 profiles dil_mma_k.
// ---------------------------------------------------------------------------

#define T_LEN 8192
#define NB    2
#define RC    512
#define SC    256
#define NL    30

#define SROW   144              // 72 bf16 per row (conflict-free ldmatrix)
#define APLANE 18432            // 128 rows * 144 B
#define BPLANE 36864            // 256 rows * 144 B
#define STAGE  110592           // Ah | Al | Bh | Bl
#define DSMB   221184           // 2 stages
#define EPITCH 260              // f32 epilogue tile pitch

// ---- global scratch --------------------------------------------------------
__device__ __nv_bfloat16 g_Wd [(size_t)NL*3*2*1024*512]; // [l][tap][pl][cop][ci]
__device__ __nv_bfloat16 g_Wrs[(size_t)NL*2*768*512];    // [l][pl][m][ci]
__device__ __nv_bfloat16 g_xh[(size_t)NB*T_LEN*RC], g_xl[(size_t)NB*T_LEN*RC];
__device__ __nv_bfloat16 g_ah[(size_t)NB*T_LEN*RC], g_al[(size_t)NB*T_LEN*RC];
__device__ float g_skip[(size_t)NB*SC*T_LEN];            // [b][c][t]
__device__ float g_y   [(size_t)NB*SC*T_LEN];            // [b][c][t]
__device__ float g_F1p [SC*SC];                          // [ci][co]

// ---- PTX helpers -----------------------------------------------------------
__device__ __forceinline__ uint32_t smem_u32(const void* p) {
    uint32_t a;
    asm("{ .reg .u64 t; cvta.to.shared.u64 t, %1; cvt.u32.u64 %0, t; }"
        : "=r"(a) : "l"(p));
    return a;
}
__device__ __forceinline__ void cp16(uint32_t dst, const void* src) {
    asm volatile("cp.async.ca.shared.global [%0], [%1], 16;"
                 :: "r"(dst), "l"(src));
}
__device__ __forceinline__ void cp16z(uint32_t dst, const void* src, int ok) {
    int sz = ok ? 16 : 0;
    asm volatile("cp.async.ca.shared.global [%0], [%1], 16, %2;"
                 :: "r"(dst), "l"(src), "r"(sz));
}
#define CP_COMMIT() asm volatile("cp.async.commit_group;" ::: "memory")
#define CP_WAIT1()  asm volatile("cp.async.wait_group 1;" ::: "memory")
#define CP_WAIT0()  asm volatile("cp.async.wait_group 0;" ::: "memory")

__device__ __forceinline__ void ldsm4(uint32_t* r, uint32_t a) {
    asm volatile("ldmatrix.sync.aligned.m8n8.x4.shared.b16 {%0,%1,%2,%3}, [%4];"
                 : "=r"(r[0]), "=r"(r[1]), "=r"(r[2]), "=r"(r[3]) : "r"(a));
}
__device__ __forceinline__ void mma16816(float* c, const uint32_t* a,
                                         uint32_t b0, uint32_t b1) {
    asm volatile(
        "mma.sync.aligned.m16n8k16.row.col.f32.bf16.bf16.f32 "
        "{%0,%1,%2,%3},{%4,%5,%6,%7},{%8,%9},{%0,%1,%2,%3};"
        : "+f"(c[0]), "+f"(c[1]), "+f"(c[2]), "+f"(c[3])
        : "r"(a[0]), "r"(a[1]), "r"(a[2]), "r"(a[3]), "r"(b0), "r"(b1));
}

__device__ __forceinline__ float gatefn(float f, float g) {
    float ef = __expf(2.f * f);
    float th = 1.f - __fdividef(2.f, ef + 1.f);
    float sg = __fdividef(1.f, 1.f + __expf(-g));
    return th * sg;
}
__device__ __forceinline__ void split_store(__nv_bfloat16* ph, __nv_bfloat16* pl,
                                            size_t o, float v) {
    __nv_bfloat16 h = __float2bfloat16(v);
    ph[o] = h;
    pl[o] = __float2bfloat16(v - __bfloat162float(h));
}

// ---- one K-chunk (64 ci) of hi/lo 3-pass MMA, tile 128x256 ----------------
// Stage base sb: Ah +0, Al +APLANE, Bh +2*APLANE, Bl +2*APLANE+BPLANE.
// Warp (wm=wid&3, wn=wid>>2): rows [wm*32,+32), cols [wn*128,+128).
__device__ __forceinline__ void chunk_mma(float acc[2][16][4], uint32_t sb,
                                          int wm, int wn, uint32_t laneOff) {
    const uint32_t aB = sb, bB = sb + 2 * APLANE;
    #pragma unroll
    for (int ks = 0; ks < 4; ks++) {
        const uint32_t kx = ks * 32 + laneOff;
        uint32_t aH[2][4], aL[2][4];
        #pragma unroll
        for (int mi = 0; mi < 2; mi++) {
            uint32_t ra = aB + (wm * 32 + mi * 16) * SROW + kx;
            ldsm4(aH[mi], ra);
            ldsm4(aL[mi], ra + APLANE);
        }
        #pragma unroll
        for (int np = 0; np < 8; np++) {
            uint32_t bH[4], bL[4];
            uint32_t rb = bB + (wn * 128 + np * 16) * SROW + kx;
            ldsm4(bH, rb);
            ldsm4(bL, rb + BPLANE);
            #pragma unroll
            for (int mi = 0; mi < 2; mi++) {
                mma16816(acc[mi][2 * np],     aH[mi], bH[0], bH[2]);
                mma16816(acc[mi][2 * np + 1], aH[mi], bH[1], bH[3]);
                mma16816(acc[mi][2 * np],     aH[mi], bL[0], bL[2]);
                mma16816(acc[mi][2 * np + 1], aH[mi], bL[1], bL[3]);
                mma16816(acc[mi][2 * np],     aL[mi], bH[0], bH[2]);
                mma16816(acc[mi][2 * np + 1], aL[mi], bH[1], bH[3]);
            }
        }
    }
}

// Store warp accumulators to f32 smem tile [128][EPITCH].
__device__ __forceinline__ void acc_to_smem(float* sE, float acc[2][16][4],
                                            int wm, int wn, int lane) {
    int r0 = wm * 32 + (lane >> 2);
    int cb = wn * 128 + (lane & 3) * 2;
    #pragma unroll
    for (int mi = 0; mi < 2; mi++)
        #pragma unroll
        for (int ni = 0; ni < 16; ni++) {
            int rr = r0 + mi * 16, cc = cb + ni * 8;
            sE[rr * EPITCH + cc]           = acc[mi][ni][0];
            sE[rr * EPITCH + cc + 1]       = acc[mi][ni][1];
            sE[(rr + 8) * EPITCH + cc]     = acc[mi][ni][2];
            sE[(rr + 8) * EPITCH + cc + 1] = acc[mi][ni][3];
        }
}

// ---- weight prep -----------------------------------------------------------
__global__ void prep_dil_k(const float* __restrict__ dil_w) {
    int idx = blockIdx.x * 256 + threadIdx.x;   // 15,728,640 (l,co,ci)
    int ci = idx & 511;
    int r = idx >> 9;
    int co = r & 1023;
    int l = r >> 10;
    const float* s = dil_w + ((size_t)(l * 1024 + co) * 512 + ci) * 3;
    int cop;
    if (co < 512) cop = (co >> 6) * 128 + (co & 63);
    else { int c = co - 512; cop = (c >> 6) * 128 + 64 + (c & 63); }
    #pragma unroll
    for (int tap = 0; tap < 3; tap++) {
        float w = s[tap];
        __nv_bfloat16 h = __float2bfloat16(w);
        __nv_bfloat16 lo = __float2bfloat16(w - __bfloat162float(h));
        size_t base = ((size_t)(l * 3 + tap) * 2) * 1024 * 512
                      + (size_t)cop * 512 + ci;
        g_Wd[base] = h;
        g_Wd[base + (size_t)1024 * 512] = lo;
    }
}

// prep res/skip weights + transposed fc1 (merged to save a launch slot)
__global__ void prep_rs_k(const float* __restrict__ res_w,
                          const float* __restrict__ skip_w,
                          const float* __restrict__ fc1_w) {
    int idx = blockIdx.x * 256 + threadIdx.x;
    if (idx < 11796480) {
        int ci = idx & 511;
        int r = idx >> 9;
        int m = r % 768, l = r / 768;
        float w = (m < 512) ? res_w[((size_t)(l * 512 + m)) * 512 + ci]
                            : skip_w[((size_t)(l * 256 + m - 512)) * 512 + ci];
        __nv_bfloat16 h = __float2bfloat16(w);
        __nv_bfloat16 lo = __float2bfloat16(w - __bfloat162float(h));
        size_t base = ((size_t)(l * 2) * 768 + m) * 512 + ci;
        g_Wrs[base] = h;
        g_Wrs[base + (size_t)768 * 512] = lo;
    } else {
        int k = idx - 11796480;
        if (k < 65536) {
            int co = k & 255, ci = k >> 8;
            g_F1p[ci * 256 + co] = fc1_w[co * 256 + ci];
        }
    }
}

// ---- init: x[t][c] = start_w*audio + mel 1x1 + biases (hi/lo split) --------
__global__ __launch_bounds__(256) void init_x_k(
        const float* __restrict__ mel, const float* __restrict__ audio,
        const float* __restrict__ start_w, const float* __restrict__ start_b,
        const float* __restrict__ mel_w, const float* __restrict__ mel_b) {
    extern __shared__ float ism[];
    float* wsm  = ism;                 // [64][81]
    float* mels = ism + 64 * 81;       // [80][129]
    __shared__ float auds[128];
    const int tid = threadIdx.x;
    const int t0 = blockIdx.x * 128, b = blockIdx.y, cb = blockIdx.z * 64;
    for (int i = tid; i < 64 * 80; i += 256) {
        int c = i / 80, m = i % 80;
        wsm[c * 81 + m] = mel_w[(size_t)(cb + c) * 80 + m];
    }
    for (int i = tid; i < 80 * 128; i += 256) {
        int m = i >> 7, t = i & 127;
        mels[m * 129 + t] = mel[((size_t)(b * 80 + m)) * T_LEN + t0 + t];
    }
    if (tid < 128) auds[tid] = audio[(size_t)b * T_LEN + t0 + tid];
    __syncthreads();
    const int c_l = tid & 63, tg = tid >> 6;
    const int c = cb + c_l;
    const float sw = start_w[c], bb = start_b[c] + mel_b[c];
    for (int ti = 0; ti < 32; ti++) {
        int t = tg * 32 + ti;
        float acc = bb + sw * auds[t];
        #pragma unroll 8
        for (int m = 0; m < 80; m++) acc += wsm[c_l * 81 + m] * mels[m * 129 + t];
        split_store(g_xh, g_xl, ((size_t)b * T_LEN + t0 + t) * RC + c, acc);
    }
}

// ---- dilated conv + gate ---------------------------------------------------
__device__ __forceinline__ void dil_load_chunk(uint32_t sb,
        int layer, int tap, int ci0, int t0, int b, int mt, int dil, int tid) {
    const __nv_bfloat16* wl = g_Wd + ((size_t)(layer * 3 + tap) * 2) * 1024 * 512;
    #pragma unroll
    for (int p = 0; p < 8; p++) {                       // A: 2048 16B chunks
        int idx = tid + p * 256;
        int pl = idx >> 10, rem = idx & 1023, r = rem >> 3, j = rem & 7;
        const __nv_bfloat16* src = wl + ((size_t)pl * 1024 + mt * 128 + r) * 512
                                      + ci0 + j * 8;
        cp16(sb + pl * APLANE + r * SROW + j * 16, src);
    }
    int shift = (tap - 1) * dil;
    #pragma unroll
    for (int p = 0; p < 16; p++) {                      // B: 4096 16B chunks
        int idx = tid + p * 256;
        int pl = idx >> 11, rem = idx & 2047, r = rem >> 3, j = rem & 7;
        int t = t0 + r + shift;
        int ok = (t >= 0 && t < T_LEN);
        const __nv_bfloat16* plane = pl ? g_xl : g_xh;
        const __nv_bfloat16* src = plane + ((size_t)b * T_LEN + (ok ? t : 0)) * RC
                                        + ci0 + j * 8;
        cp16z(sb + 2 * APLANE + pl * BPLANE + r * SROW + j * 16, src, ok);
    }
}

__global__ __launch_bounds__(256, 1) void dil_mma_k(
        const float* __restrict__ dil_b, int layer, int dil) {
    extern __shared__ char dsm[];
    const int tid = threadIdx.x, wid = tid >> 5, lane = tid & 31;
    const int wm = wid & 3, wn = wid >> 2;
    const int mt = blockIdx.z, b = blockIdx.y, t0 = blockIdx.x * 256;
    const uint32_t dsm0 = smem_u32(dsm);
    const uint32_t laneOff = (lane & 15) * SROW + (lane >> 4) * 16;

    float acc[2][16][4];
    #pragma unroll
    for (int i = 0; i < 2; i++)
        #pragma unroll
        for (int j = 0; j < 16; j++)
            #pragma unroll
            for (int k = 0; k < 4; k++) acc[i][j][k] = 0.f;

    const int NCH = 24;
    dil_load_chunk(dsm0, layer, 0, 0, t0, b, mt, dil, tid);
    CP_COMMIT();
    for (int it = 0; it < NCH; it++) {
        if (it + 1 < NCH) {
            int nc = it + 1;
            dil_load_chunk(dsm0 + (nc & 1) * STAGE, layer, nc >> 3,
                           (nc & 7) * 64, t0, b, mt, dil, tid);
            CP_COMMIT();
            CP_WAIT1();
        } else {
            CP_WAIT0();
        }
        __syncthreads();
        chunk_mma(acc, dsm0 + (it & 1) * STAGE, wm, wn, laneOff);
        __syncthreads();
    }

    float* sE = (float*)dsm;
    acc_to_smem(sE, acc, wm, wn, lane);
    __syncthreads();

    const int c_l = tid & 63, tg = tid >> 6;
    const float bf = dil_b[layer * 1024 + mt * 64 + c_l];
    const float bg = dil_b[layer * 1024 + 512 + mt * 64 + c_l];
    const size_t rb = (size_t)b * T_LEN + t0;
    for (int ti = 0; ti < 64; ti++) {
        int t = tg * 64 + ti;
        float f = sE[c_l * EPITCH + t] + bf;
        float g = sE[(64 + c_l) * EPITCH + t] + bg;
        split_store(g_ah, g_al, (rb + t) * RC + mt * 64 + c_l, gatefn(f, g));
    }
}

// ---- fused res + skip ------------------------------------------------------
__global__ __launch_bounds__(256, 1) void res_mma_k(
        const float* __restrict__ res_b, const float* __restrict__ skip_b,
        int layer) {
    extern __shared__ char dsm[];
    const int tid = threadIdx.x, wid = tid >> 5, lane = tid & 31;
    const int wm = wid & 3, wn = wid >> 2;
    const int m0 = blockIdx.z * 128, b = blockIdx.y, t0 = blockIdx.x * 256;
    const uint32_t dsm0 = smem_u32(dsm);
    const uint32_t laneOff = (lane & 15) * SROW + (lane >> 4) * 16;

    float acc[2][16][4];
    #pragma unroll
    for (int i = 0; i < 2; i++)
        #pragma unroll
        for (int j = 0; j < 16; j++)
            #pragma unroll
            for (int k = 0; k < 4; k++) acc[i][j][k] = 0.f;

    const __nv_bfloat16* wl = g_Wrs + (size_t)(layer * 2) * 768 * 512;

    auto load_chunk = [&](uint32_t sb, int ci0) {
        #pragma unroll
        for (int p = 0; p < 8; p++) {
            int idx = tid + p * 256;
            int pl = idx >> 10, rem = idx & 1023, r = rem >> 3, j = rem & 7;
            const __nv_bfloat16* src = wl + ((size_t)pl * 768 + m0 + r) * 512
                                          + ci0 + j * 8;
            cp16(sb + pl * APLANE + r * SROW + j * 16, src);
        }
        #pragma unroll
        for (int p = 0; p < 16; p++) {
            int idx = tid + p * 256;
            int pl = idx >> 11, rem = idx & 2047, r = rem >> 3, j = rem & 7;
            const __nv_bfloat16* plane = pl ? g_al : g_ah;
            const __nv_bfloat16* src = plane + ((size_t)b * T_LEN + t0 + r) * RC
                                            + ci0 + j * 8;
            cp16(sb + 2 * APLANE + pl * BPLANE + r * SROW + j * 16, src);
        }
    };

    const int NCH = 8;
    load_chunk(dsm0, 0);
    CP_COMMIT();
    for (int it = 0; it < NCH; it++) {
        if (it + 1 < NCH) {
            load_chunk(dsm0 + ((it + 1) & 1) * STAGE, (it + 1) * 64);
            CP_COMMIT();
            CP_WAIT1();
        } else {
            CP_WAIT0();
        }
        __syncthreads();
        chunk_mma(acc, dsm0 + (it & 1) * STAGE, wm, wn, laneOff);
        __syncthreads();
    }

    float* sE = (float*)dsm;
    acc_to_smem(sE, acc, wm, wn, lane);
    __syncthreads();

    if (m0 < 512) {             // residual: x += d + bias (re-split hi/lo)
        const int c_l = tid & 127, tg = tid >> 7;
        const float rb = res_b[layer * 512 + m0 + c_l];
        for (int ti = 0; ti < 128; ti++) {
            int t = tg * 128 + ti;
            float d = sE[c_l * EPITCH + t] + rb;
            size_t o = ((size_t)b * T_LEN + t0 + t) * RC + m0 + c_l;
            float nx = __bfloat162float(g_xh[o]) + __bfloat162float(g_xl[o]) + d;
            split_store(g_xh, g_xl, o, nx);
        }
    } else {                    // skip accumulate ([b][c][t]); layer 0 stores
        const int c0 = m0 - 512;
        for (int c = 0; c < 128; c++) {
            float sb2 = skip_b[layer * 256 + c0 + c];
            float v = sE[c * EPITCH + tid] + sb2;
            float* dst = g_skip + ((size_t)b * 256 + c0 + c) * T_LEN + t0 + tid;
            if (layer == 0) *dst = v;
            else            *dst += v;
        }
    }
}

// ---- fc1 (fp32 FFMA2 GEMM) -------------------------------------------------
__device__ __forceinline__ void ffma2(unsigned long long& d, unsigned long long a,
                                      unsigned long long b) {
    asm("fma.rn.f32x2 %0, %1, %2, %0;" : "+l"(d) : "l"(a), "l"(b));
}
__device__ __forceinline__ unsigned long long pack2(float v) {
    unsigned long long r; unsigned u = __float_as_uint(v);
    asm("mov.b64 %0, {%1, %1};" : "=l"(r) : "r"(u));
    return r;
}
__device__ __forceinline__ float lo2(unsigned long long v) {
    return __uint_as_float((unsigned)v);
}
__device__ __forceinline__ float hi2(unsigned long long v) {
    return __uint_as_float((unsigned)(v >> 32));
}

__global__ __launch_bounds__(256) void fc1_gemm_k(const float* __restrict__ fc1_b) {
    __shared__ __align__(16) float Ws[16][128];
    __shared__ __align__(16) float Xs[16][128];
    const int tid = threadIdx.x, tx = tid & 15, ty = tid >> 4;
    const int t0 = blockIdx.x * 128, b = blockIdx.y, m0 = blockIdx.z * 128;
    const float* __restrict__ sin_ = g_skip + (size_t)b * (SC * T_LEN);

    unsigned long long acc[8][4];
    #pragma unroll
    for (int i = 0; i < 8; i++)
        #pragma unroll
        for (int j = 0; j < 4; j++) acc[i][j] = 0ull;

    float pw[8], px[8];
    #pragma unroll
    for (int l = 0; l < 8; l++) {
        int idx = tid + l * 256, r = idx >> 7, m = idx & 127;
        pw[l] = g_F1p[r * 256 + m0 + m];
        px[l] = sin_[r * T_LEN + t0 + m];
    }
    for (int it = 0; it < 16; ++it) {
        #pragma unroll
        for (int l = 0; l < 8; l++) {
            int idx = tid + l * 256, r = idx >> 7, m = idx & 127;
            Ws[r][m] = pw[l];
            Xs[r][m] = px[l];
        }
        __syncthreads();
        if (it + 1 < 16) {
            int kc = (it + 1) * 16;
            #pragma unroll
            for (int l = 0; l < 8; l++) {
                int idx = tid + l * 256, r = idx >> 7, m = idx & 127;
                pw[l] = g_F1p[(kc + r) * 256 + m0 + m];
                px[l] = sin_[(kc + r) * T_LEN + t0 + m];
            }
        }
        #pragma unroll
        for (int k = 0; k < 16; k++) {
            const float4 wa = *(const float4*)&Ws[k][ty * 4];
            const float4 wb = *(const float4*)&Ws[k][64 + ty * 4];
            const ulonglong2 xA = *(const ulonglong2*)&Xs[k][tx * 4];
            const ulonglong2 xB = *(const ulonglong2*)&Xs[k][64 + tx * 4];
            unsigned long long xf[4] = {xA.x, xA.y, xB.x, xB.y};
            float wv[8] = {wa.x, wa.y, wa.z, wa.w, wb.x, wb.y, wb.z, wb.w};
            #pragma unroll
            for (int i = 0; i < 8; i++) {
                unsigned long long wp = pack2(wv[i]);
                #pragma unroll
                for (int j = 0; j < 4; j++) ffma2(acc[i][j], wp, xf[j]);
            }
        }
        __syncthreads();
    }
    #pragma unroll
    for (int i = 0; i < 8; i++) {
        int ml = (i < 4) ? (ty * 4 + i) : (64 + ty * 4 + (i - 4));
        int m = m0 + ml;
        float bias = fc1_b[m];
        float* ptr = g_y + ((size_t)(b * 256 + m)) * T_LEN + t0;
        float4 v;
        v.x = fmaxf(lo2(acc[i][0]) + bias, 0.f);
        v.y = fmaxf(hi2(acc[i][0]) + bias, 0.f);
        v.z = fmaxf(lo2(acc[i][1]) + bias, 0.f);
        v.w = fmaxf(hi2(acc[i][1]) + bias, 0.f);
        *(float4*)&ptr[tx * 4] = v;
        float4 u;
        u.x = fmaxf(lo2(acc[i][2]) + bias, 0.f);
        u.y = fmaxf(hi2(acc[i][2]) + bias, 0.f);
        u.z = fmaxf(lo2(acc[i][3]) + bias, 0.f);
        u.w = fmaxf(hi2(acc[i][3]) + bias, 0.f);
        *(float4*)&ptr[64 + tx * 4] = u;
    }
}

__global__ void fc2_k(const float* __restrict__ fc2_w,
                      const float* __restrict__ fc2_b,
                      float* __restrict__ out) {
    int b = blockIdx.y;
    int t = blockIdx.x * 256 + threadIdx.x;
    const float* yb = g_y + (size_t)b * (SC * T_LEN) + t;
    float s = fc2_b[0];
    #pragma unroll 8
    for (int c = 0; c < SC; c++) s += fc2_w[c] * yb[(size_t)c * T_LEN];
    out[b * T_LEN + t] = tanhf(s);
}

// ---------------------------------------------------------------------------
extern "C" void kernel_launch(void* const* d_in, const int* in_sizes, int n_in,
                              void* d_out, int out_size) {
    (void)in_sizes; (void)n_in; (void)out_size;
    const float* mel     = (const float*)d_in[0];
    const float* audio   = (const float*)d_in[1];
    const float* start_w = (const float*)d_in[2];
    const float* start_b = (const float*)d_in[3];
    const float* mel_w   = (const float*)d_in[4];
    const float* mel_b   = (const float*)d_in[5];
    const float* dil_w   = (const float*)d_in[6];
    const float* dil_b   = (const float*)d_in[7];
    const float* res_w   = (const float*)d_in[8];
    const float* res_b   = (const float*)d_in[9];
    const float* skip_w  = (const float*)d_in[10];
    const float* skip_b  = (const float*)d_in[11];
    const float* fc1_w   = (const float*)d_in[12];
    const float* fc1_b   = (const float*)d_in[13];
    const float* fc2_w   = (const float*)d_in[14];
    const float* fc2_b   = (const float*)d_in[15];
    float* out = (float*)d_out;

    static int s_attr_done = 0;
    if (!s_attr_done) {
        cudaFuncSetAttribute(dil_mma_k, cudaFuncAttributeMaxDynamicSharedMemorySize, DSMB);
        cudaFuncSetAttribute(res_mma_k, cudaFuncAttributeMaxDynamicSharedMemorySize, DSMB);
        cudaFuncSetAttribute(init_x_k, cudaFuncAttributeMaxDynamicSharedMemorySize, 65536);
        s_attr_done = 1;
    }

    // 3 setup launches, then dil layer 0 (so ncu -s5 lands on a dil launch
    // given the harness's ~2 preceding utility launches).
    prep_dil_k<<<61440, 256>>>(dil_w);
    prep_rs_k <<<46336, 256>>>(res_w, skip_w, fc1_w);
    init_x_k<<<dim3(64, 2, 8), 256, (64 * 81 + 80 * 129) * 4>>>(
        mel, audio, start_w, start_b, mel_w, mel_b);

    for (int l = 0; l < NL; l++) {
        int d = 1 << (l % 10);
        dil_mma_k<<<dim3(32, 2, 8), 256, DSMB>>>(dil_b, l, d);
        res_mma_k<<<dim3(32, 2, 6), 256, DSMB>>>(res_b, skip_b, l);
    }
    fc1_gemm_k<<<dim3(64, 2, 2), 256>>>(fc1_b);
    fc2_k<<<dim3(32, 2), 256>>>(fc2_w, fc2_b, out);
}

// round 12
// speedup vs baseline: 1.7921x; 1.7921x over previous
#include <cuda_runtime.h>
#include <cuda_bf16.h>
#include <cstdint>

// ---------------------------------------------------------------------------
// WaveNet vocoder via mma.sync bf16 (hi/lo split, 3 passes) — sm_103-safe PTX.
// R8: R7 (512 threads / 16 warps, warp tile 32x32, 128x128 CTA tile,
// SROW=144, 2-stage cp.async) + fixed skip-epilogue block offset.
// ---------------------------------------------------------------------------

#define T_LEN 8192
#define NB    2
#define RC    512
#define SC    256
#define NL    30

#define SROW   144              // 72 bf16 per row (conflict-free ldmatrix)
#define APLANE 18432            // 128 rows * 144 B
#define STAGE  73728            // Ah | Al | Bh | Bl
#define DSMB   147456           // 2 stages
#define NTHR   512

// ---- global scratch --------------------------------------------------------
__device__ __nv_bfloat16 g_Wd [(size_t)NL*3*2*1024*512]; // [l][tap][pl][cop][ci]
__device__ __nv_bfloat16 g_Wrs[(size_t)NL*2*768*512];    // [l][pl][m][ci]
__device__ __nv_bfloat16 g_xh[(size_t)NB*T_LEN*RC], g_xl[(size_t)NB*T_LEN*RC];
__device__ __nv_bfloat16 g_ah[(size_t)NB*T_LEN*RC], g_al[(size_t)NB*T_LEN*RC];
__device__ float g_skip[(size_t)NB*SC*T_LEN];            // [b][c][t]
__device__ float g_y   [(size_t)NB*SC*T_LEN];            // [b][c][t]
__device__ float g_F1p [SC*SC];                          // [ci][co]

// ---- PTX helpers -----------------------------------------------------------
__device__ __forceinline__ uint32_t smem_u32(const void* p) {
    uint32_t a;
    asm("{ .reg .u64 t; cvta.to.shared.u64 t, %1; cvt.u32.u64 %0, t; }"
        : "=r"(a) : "l"(p));
    return a;
}
__device__ __forceinline__ void cp16(uint32_t dst, const void* src) {
    asm volatile("cp.async.ca.shared.global [%0], [%1], 16;"
                 :: "r"(dst), "l"(src));
}
__device__ __forceinline__ void cp16z(uint32_t dst, const void* src, int ok) {
    int sz = ok ? 16 : 0;
    asm volatile("cp.async.ca.shared.global [%0], [%1], 16, %2;"
                 :: "r"(dst), "l"(src), "r"(sz));
}
#define CP_COMMIT() asm volatile("cp.async.commit_group;" ::: "memory")
#define CP_WAIT1()  asm volatile("cp.async.wait_group 1;" ::: "memory")
#define CP_WAIT0()  asm volatile("cp.async.wait_group 0;" ::: "memory")

__device__ __forceinline__ void ldsm4(uint32_t* r, uint32_t a) {
    asm volatile("ldmatrix.sync.aligned.m8n8.x4.shared.b16 {%0,%1,%2,%3}, [%4];"
                 : "=r"(r[0]), "=r"(r[1]), "=r"(r[2]), "=r"(r[3]) : "r"(a));
}
__device__ __forceinline__ void mma16816(float* c, const uint32_t* a,
                                         uint32_t b0, uint32_t b1) {
    asm volatile(
        "mma.sync.aligned.m16n8k16.row.col.f32.bf16.bf16.f32 "
        "{%0,%1,%2,%3},{%4,%5,%6,%7},{%8,%9},{%0,%1,%2,%3};"
        : "+f"(c[0]), "+f"(c[1]), "+f"(c[2]), "+f"(c[3])
        : "r"(a[0]), "r"(a[1]), "r"(a[2]), "r"(a[3]), "r"(b0), "r"(b1));
}

__device__ __forceinline__ float gatefn(float f, float g) {
    float ef = __expf(2.f * f);
    float th = 1.f - __fdividef(2.f, ef + 1.f);
    float sg = __fdividef(1.f, 1.f + __expf(-g));
    return th * sg;
}
__device__ __forceinline__ void split_store(__nv_bfloat16* ph, __nv_bfloat16* pl,
                                            size_t o, float v) {
    __nv_bfloat16 h = __float2bfloat16(v);
    ph[o] = h;
    pl[o] = __float2bfloat16(v - __bfloat162float(h));
}

// ---- one K-chunk (64 ci) of hi/lo 3-pass MMA, warp tile 32x32 -------------
// Stage base sb: Ah +0, Al +APLANE, Bh +2*APLANE, Bl +3*APLANE.
// Warp (wm=wid&3, wn=wid>>2): rows [wm*32,+32), cols [wn*32,+32).
__device__ __forceinline__ void chunk_mma(float acc[2][4][4], uint32_t sb,
                                          int wm, int wn, uint32_t laneOff) {
    const uint32_t aB = sb, bB = sb + 2 * APLANE;
    #pragma unroll
    for (int ks = 0; ks < 4; ks++) {
        const uint32_t kx = ks * 32 + laneOff;
        uint32_t aH[2][4], aL[2][4], bH[2][4], bL[2][4];
        #pragma unroll
        for (int mi = 0; mi < 2; mi++) {
            uint32_t ra = aB + (wm * 32 + mi * 16) * SROW + kx;
            ldsm4(aH[mi], ra);
            ldsm4(aL[mi], ra + APLANE);
        }
        #pragma unroll
        for (int np = 0; np < 2; np++) {
            uint32_t rb = bB + (wn * 32 + np * 16) * SROW + kx;
            ldsm4(bH[np], rb);
            ldsm4(bL[np], rb + APLANE);
        }
        #pragma unroll
        for (int mi = 0; mi < 2; mi++)
            #pragma unroll
            for (int np = 0; np < 2; np++) {
                mma16816(acc[mi][2 * np],     aH[mi], bH[np][0], bH[np][2]);
                mma16816(acc[mi][2 * np + 1], aH[mi], bH[np][1], bH[np][3]);
                mma16816(acc[mi][2 * np],     aH[mi], bL[np][0], bL[np][2]);
                mma16816(acc[mi][2 * np + 1], aH[mi], bL[np][1], bL[np][3]);
                mma16816(acc[mi][2 * np],     aL[mi], bH[np][0], bH[np][2]);
                mma16816(acc[mi][2 * np + 1], aL[mi], bH[np][1], bH[np][3]);
            }
    }
}

// Store warp accumulators to f32 smem tile [128][132].
__device__ __forceinline__ void acc_to_smem(float* sE, float acc[2][4][4],
                                            int wm, int wn, int lane) {
    int r0 = wm * 32 + (lane >> 2);
    int cb = wn * 32 + (lane & 3) * 2;
    #pragma unroll
    for (int mi = 0; mi < 2; mi++)
        #pragma unroll
        for (int ni = 0; ni < 4; ni++) {
            int rr = r0 + mi * 16, cc = cb + ni * 8;
            sE[rr * 132 + cc]           = acc[mi][ni][0];
            sE[rr * 132 + cc + 1]       = acc[mi][ni][1];
            sE[(rr + 8) * 132 + cc]     = acc[mi][ni][2];
            sE[(rr + 8) * 132 + cc + 1] = acc[mi][ni][3];
        }
}

// ---- weight prep -----------------------------------------------------------
__global__ void prep_dil_k(const float* __restrict__ dil_w) {
    int idx = blockIdx.x * 256 + threadIdx.x;   // 15,728,640 (l,co,ci)
    int ci = idx & 511;
    int r = idx >> 9;
    int co = r & 1023;
    int l = r >> 10;
    const float* s = dil_w + ((size_t)(l * 1024 + co) * 512 + ci) * 3;
    int cop;
    if (co < 512) cop = (co >> 6) * 128 + (co & 63);
    else { int c = co - 512; cop = (c >> 6) * 128 + 64 + (c & 63); }
    #pragma unroll
    for (int tap = 0; tap < 3; tap++) {
        float w = s[tap];
        __nv_bfloat16 h = __float2bfloat16(w);
        __nv_bfloat16 lo = __float2bfloat16(w - __bfloat162float(h));
        size_t base = ((size_t)(l * 3 + tap) * 2) * 1024 * 512
                      + (size_t)cop * 512 + ci;
        g_Wd[base] = h;
        g_Wd[base + (size_t)1024 * 512] = lo;
    }
}

// prep res/skip weights + transposed fc1 (merged)
__global__ void prep_rs_k(const float* __restrict__ res_w,
                          const float* __restrict__ skip_w,
                          const float* __restrict__ fc1_w) {
    int idx = blockIdx.x * 256 + threadIdx.x;
    if (idx < 11796480) {
        int ci = idx & 511;
        int r = idx >> 9;
        int m = r % 768, l = r / 768;
        float w = (m < 512) ? res_w[((size_t)(l * 512 + m)) * 512 + ci]
                            : skip_w[((size_t)(l * 256 + m - 512)) * 512 + ci];
        __nv_bfloat16 h = __float2bfloat16(w);
        __nv_bfloat16 lo = __float2bfloat16(w - __bfloat162float(h));
        size_t base = ((size_t)(l * 2) * 768 + m) * 512 + ci;
        g_Wrs[base] = h;
        g_Wrs[base + (size_t)768 * 512] = lo;
    } else {
        int k = idx - 11796480;
        if (k < 65536) {
            int co = k & 255, ci = k >> 8;
            g_F1p[ci * 256 + co] = fc1_w[co * 256 + ci];
        }
    }
}

// ---- init: x[t][c] = start_w*audio + mel 1x1 + biases (hi/lo split) --------
__global__ __launch_bounds__(256) void init_x_k(
        const float* __restrict__ mel, const float* __restrict__ audio,
        const float* __restrict__ start_w, const float* __restrict__ start_b,
        const float* __restrict__ mel_w, const float* __restrict__ mel_b) {
    extern __shared__ float ism[];
    float* wsm  = ism;                 // [64][81]
    float* mels = ism + 64 * 81;       // [80][129]
    __shared__ float auds[128];
    const int tid = threadIdx.x;
    const int t0 = blockIdx.x * 128, b = blockIdx.y, cb = blockIdx.z * 64;
    for (int i = tid; i < 64 * 80; i += 256) {
        int c = i / 80, m = i % 80;
        wsm[c * 81 + m] = mel_w[(size_t)(cb + c) * 80 + m];
    }
    for (int i = tid; i < 80 * 128; i += 256) {
        int m = i >> 7, t = i & 127;
        mels[m * 129 + t] = mel[((size_t)(b * 80 + m)) * T_LEN + t0 + t];
    }
    if (tid < 128) auds[tid] = audio[(size_t)b * T_LEN + t0 + tid];
    __syncthreads();
    const int c_l = tid & 63, tg = tid >> 6;
    const int c = cb + c_l;
    const float sw = start_w[c], bb = start_b[c] + mel_b[c];
    for (int ti = 0; ti < 32; ti++) {
        int t = tg * 32 + ti;
        float acc = bb + sw * auds[t];
        #pragma unroll 8
        for (int m = 0; m < 80; m++) acc += wsm[c_l * 81 + m] * mels[m * 129 + t];
        split_store(g_xh, g_xl, ((size_t)b * T_LEN + t0 + t) * RC + c, acc);
    }
}

// ---- dilated conv + gate ---------------------------------------------------
__device__ __forceinline__ void dil_load_chunk(uint32_t sb,
        int layer, int tap, int ci0, int t0, int b, int mt, int dil, int tid) {
    const __nv_bfloat16* wl = g_Wd + ((size_t)(layer * 3 + tap) * 2) * 1024 * 512;
    #pragma unroll
    for (int p = 0; p < 4; p++) {                       // A: 2048 16B chunks
        int idx = tid + p * NTHR;
        int pl = idx >> 10, rem = idx & 1023, r = rem >> 3, j = rem & 7;
        const __nv_bfloat16* src = wl + ((size_t)pl * 1024 + mt * 128 + r) * 512
                                      + ci0 + j * 8;
        cp16(sb + pl * APLANE + r * SROW + j * 16, src);
    }
    int shift = (tap - 1) * dil;
    #pragma unroll
    for (int p = 0; p < 4; p++) {                       // B: 2048 16B chunks
        int idx = tid + p * NTHR;
        int pl = idx >> 10, rem = idx & 1023, r = rem >> 3, j = rem & 7;
        int t = t0 + r + shift;
        int ok = (t >= 0 && t < T_LEN);
        const __nv_bfloat16* plane = pl ? g_xl : g_xh;
        const __nv_bfloat16* src = plane + ((size_t)b * T_LEN + (ok ? t : 0)) * RC
                                        + ci0 + j * 8;
        cp16z(sb + 2 * APLANE + pl * APLANE + r * SROW + j * 16, src, ok);
    }
}

__global__ __launch_bounds__(NTHR) void dil_mma_k(
        const float* __restrict__ dil_b, int layer, int dil) {
    extern __shared__ char dsm[];
    const int tid = threadIdx.x, wid = tid >> 5, lane = tid & 31;
    const int wm = wid & 3, wn = wid >> 2;
    const int mt = blockIdx.z, b = blockIdx.y, t0 = blockIdx.x * 128;
    const uint32_t dsm0 = smem_u32(dsm);
    const uint32_t laneOff = (lane & 15) * SROW + (lane >> 4) * 16;

    float acc[2][4][4];
    #pragma unroll
    for (int i = 0; i < 2; i++)
        #pragma unroll
        for (int j = 0; j < 4; j++)
            #pragma unroll
            for (int k = 0; k < 4; k++) acc[i][j][k] = 0.f;

    const int NCH = 24;
    dil_load_chunk(dsm0, layer, 0, 0, t0, b, mt, dil, tid);
    CP_COMMIT();
    for (int it = 0; it < NCH; it++) {
        if (it + 1 < NCH) {
            int nc = it + 1;
            dil_load_chunk(dsm0 + (nc & 1) * STAGE, layer, nc >> 3,
                           (nc & 7) * 64, t0, b, mt, dil, tid);
            CP_COMMIT();
            CP_WAIT1();
        } else {
            CP_WAIT0();
        }
        __syncthreads();
        chunk_mma(acc, dsm0 + (it & 1) * STAGE, wm, wn, laneOff);
        __syncthreads();
    }

    float* sE = (float*)dsm;
    acc_to_smem(sE, acc, wm, wn, lane);
    __syncthreads();

    const int c_l = tid & 63, tg = tid >> 6;
    const float bf = dil_b[layer * 1024 + mt * 64 + c_l];
    const float bg = dil_b[layer * 1024 + 512 + mt * 64 + c_l];
    const size_t rb = (size_t)b * T_LEN + t0;
    for (int ti = 0; ti < 16; ti++) {
        int t = tg * 16 + ti;
        float f = sE[c_l * 132 + t] + bf;
        float g = sE[(64 + c_l) * 132 + t] + bg;
        split_store(g_ah, g_al, (rb + t) * RC + mt * 64 + c_l, gatefn(f, g));
    }
}

// ---- fused res + skip ------------------------------------------------------
__global__ __launch_bounds__(NTHR) void res_mma_k(
        const float* __restrict__ res_b, const float* __restrict__ skip_b,
        int layer) {
    extern __shared__ char dsm[];
    const int tid = threadIdx.x, wid = tid >> 5, lane = tid & 31;
    const int wm = wid & 3, wn = wid >> 2;
    const int m0 = blockIdx.z * 128, b = blockIdx.y, t0 = blockIdx.x * 128;
    const uint32_t dsm0 = smem_u32(dsm);
    const uint32_t laneOff = (lane & 15) * SROW + (lane >> 4) * 16;

    float acc[2][4][4];
    #pragma unroll
    for (int i = 0; i < 2; i++)
        #pragma unroll
        for (int j = 0; j < 4; j++)
            #pragma unroll
            for (int k = 0; k < 4; k++) acc[i][j][k] = 0.f;

    const __nv_bfloat16* wl = g_Wrs + (size_t)(layer * 2) * 768 * 512;

    auto load_chunk = [&](uint32_t sb, int ci0) {
        #pragma unroll
        for (int p = 0; p < 4; p++) {
            int idx = tid + p * NTHR;
            int pl = idx >> 10, rem = idx & 1023, r = rem >> 3, j = rem & 7;
            const __nv_bfloat16* src = wl + ((size_t)pl * 768 + m0 + r) * 512
                                          + ci0 + j * 8;
            cp16(sb + pl * APLANE + r * SROW + j * 16, src);
        }
        #pragma unroll
        for (int p = 0; p < 4; p++) {
            int idx = tid + p * NTHR;
            int pl = idx >> 10, rem = idx & 1023, r = rem >> 3, j = rem & 7;
            const __nv_bfloat16* plane = pl ? g_al : g_ah;
            const __nv_bfloat16* src = plane + ((size_t)b * T_LEN + t0 + r) * RC
                                            + ci0 + j * 8;
            cp16(sb + 2 * APLANE + pl * APLANE + r * SROW + j * 16, src);
        }
    };

    const int NCH = 8;
    load_chunk(dsm0, 0);
    CP_COMMIT();
    for (int it = 0; it < NCH; it++) {
        if (it + 1 < NCH) {
            load_chunk(dsm0 + ((it + 1) & 1) * STAGE, (it + 1) * 64);
            CP_COMMIT();
            CP_WAIT1();
        } else {
            CP_WAIT0();
        }
        __syncthreads();
        chunk_mma(acc, dsm0 + (it & 1) * STAGE, wm, wn, laneOff);
        __syncthreads();
    }

    float* sE = (float*)dsm;
    acc_to_smem(sE, acc, wm, wn, lane);
    __syncthreads();

    if (m0 < 512) {             // residual: x += d + bias (re-split hi/lo)
        const int c_l = tid & 127, tg = tid >> 7;
        const float rb = res_b[layer * 512 + m0 + c_l];
        for (int ti = 0; ti < 32; ti++) {
            int t = tg * 32 + ti;
            float d = sE[c_l * 132 + t] + rb;
            size_t o = ((size_t)b * T_LEN + t0 + t) * RC + m0 + c_l;
            float nx = __bfloat162float(g_xh[o]) + __bfloat162float(g_xl[o]) + d;
            split_store(g_xh, g_xl, o, nx);
        }
    } else {                    // skip accumulate ([b][c][t]); layer 0 stores
        const int c0 = m0 - 512;             // block channel offset (FIX)
        const int t_l = tid & 127, cg = tid >> 7;
        for (int c = cg * 32; c < cg * 32 + 32; c++) {
            float sb2 = skip_b[layer * 256 + c0 + c];
            float v = sE[c * 132 + t_l] + sb2;
            float* dst = g_skip + ((size_t)b * 256 + c0 + c) * T_LEN + t0 + t_l;
            if (layer == 0) *dst = v;
            else            *dst += v;
        }
    }
}

// ---- fc1 (fp32 FFMA2 GEMM) -------------------------------------------------
__device__ __forceinline__ void ffma2(unsigned long long& d, unsigned long long a,
                                      unsigned long long b) {
    asm("fma.rn.f32x2 %0, %1, %2, %0;" : "+l"(d) : "l"(a), "l"(b));
}
__device__ __forceinline__ unsigned long long pack2(float v) {
    unsigned long long r; unsigned u = __float_as_uint(v);
    asm("mov.b64 %0, {%1, %1};" : "=l"(r) : "r"(u));
    return r;
}
__device__ __forceinline__ float lo2(unsigned long long v) {
    return __uint_as_float((unsigned)v);
}
__device__ __forceinline__ float hi2(unsigned long long v) {
    return __uint_as_float((unsigned)(v >> 32));
}

__global__ __launch_bounds__(256) void fc1_gemm_k(const float* __restrict__ fc1_b) {
    __shared__ __align__(16) float Ws[16][128];
    __shared__ __align__(16) float Xs[16][128];
    const int tid = threadIdx.x, tx = tid & 15, ty = tid >> 4;
    const int t0 = blockIdx.x * 128, b = blockIdx.y, m0 = blockIdx.z * 128;
    const float* __restrict__ sin_ = g_skip + (size_t)b * (SC * T_LEN);

    unsigned long long acc[8][4];
    #pragma unroll
    for (int i = 0; i < 8; i++)
        #pragma unroll
        for (int j = 0; j < 4; j++) acc[i][j] = 0ull;

    float pw[8], px[8];
    #pragma unroll
    for (int l = 0; l < 8; l++) {
        int idx = tid + l * 256, r = idx >> 7, m = idx & 127;
        pw[l] = g_F1p[r * 256 + m0 + m];
        px[l] = sin_[r * T_LEN + t0 + m];
    }
    for (int it = 0; it < 16; ++it) {
        #pragma unroll
        for (int l = 0; l < 8; l++) {
            int idx = tid + l * 256, r = idx >> 7, m = idx & 127;
            Ws[r][m] = pw[l];
            Xs[r][m] = px[l];
        }
        __syncthreads();
        if (it + 1 < 16) {
            int kc = (it + 1) * 16;
            #pragma unroll
            for (int l = 0; l < 8; l++) {
                int idx = tid + l * 256, r = idx >> 7, m = idx & 127;
                pw[l] = g_F1p[(kc + r) * 256 + m0 + m];
                px[l] = sin_[(kc + r) * T_LEN + t0 + m];
            }
        }
        #pragma unroll
        for (int k = 0; k < 16; k++) {
            const float4 wa = *(const float4*)&Ws[k][ty * 4];
            const float4 wb = *(const float4*)&Ws[k][64 + ty * 4];
            const ulonglong2 xA = *(const ulonglong2*)&Xs[k][tx * 4];
            const ulonglong2 xB = *(const ulonglong2*)&Xs[k][64 + tx * 4];
            unsigned long long xf[4] = {xA.x, xA.y, xB.x, xB.y};
            float wv[8] = {wa.x, wa.y, wa.z, wa.w, wb.x, wb.y, wb.z, wb.w};
            #pragma unroll
            for (int i = 0; i < 8; i++) {
                unsigned long long wp = pack2(wv[i]);
                #pragma unroll
                for (int j = 0; j < 4; j++) ffma2(acc[i][j], wp, xf[j]);
            }
        }
        __syncthreads();
    }
    #pragma unroll
    for (int i = 0; i < 8; i++) {
        int ml = (i < 4) ? (ty * 4 + i) : (64 + ty * 4 + (i - 4));
        int m = m0 + ml;
        float bias = fc1_b[m];
        float* ptr = g_y + ((size_t)(b * 256 + m)) * T_LEN + t0;
        float4 v;
        v.x = fmaxf(lo2(acc[i][0]) + bias, 0.f);
        v.y = fmaxf(hi2(acc[i][0]) + bias, 0.f);
        v.z = fmaxf(lo2(acc[i][1]) + bias, 0.f);
        v.w = fmaxf(hi2(acc[i][1]) + bias, 0.f);
        *(float4*)&ptr[tx * 4] = v;
        float4 u;
        u.x = fmaxf(lo2(acc[i][2]) + bias, 0.f);
        u.y = fmaxf(hi2(acc[i][2]) + bias, 0.f);
        u.z = fmaxf(lo2(acc[i][3]) + bias, 0.f);
        u.w = fmaxf(hi2(acc[i][3]) + bias, 0.f);
        *(float4*)&ptr[64 + tx * 4] = u;
    }
}

__global__ void fc2_k(const float* __restrict__ fc2_w,
                      const float* __restrict__ fc2_b,
                      float* __restrict__ out) {
    int b = blockIdx.y;
    int t = blockIdx.x * 256 + threadIdx.x;
    const float* yb = g_y + (size_t)b * (SC * T_LEN) + t;
    float s = fc2_b[0];
    #pragma unroll 8
    for (int c = 0; c < SC; c++) s += fc2_w[c] * yb[(size_t)c * T_LEN];
    out[b * T_LEN + t] = tanhf(s);
}

// ---------------------------------------------------------------------------
extern "C" void kernel_launch(void* const* d_in, const int* in_sizes, int n_in,
                              void* d_out, int out_size) {
    (void)in_sizes; (void)n_in; (void)out_size;
    const float* mel     = (const float*)d_in[0];
    const float* audio   = (const float*)d_in[1];
    const float* start_w = (const float*)d_in[2];
    const float* start_b = (const float*)d_in[3];
    const float* mel_w   = (const float*)d_in[4];
    const float* mel_b   = (const float*)d_in[5];
    const float* dil_w   = (const float*)d_in[6];
    const float* dil_b   = (const float*)d_in[7];
    const float* res_w   = (const float*)d_in[8];
    const float* res_b   = (const float*)d_in[9];
    const float* skip_w  = (const float*)d_in[10];
    const float* skip_b  = (const float*)d_in[11];
    const float* fc1_w   = (const float*)d_in[12];
    const float* fc1_b   = (const float*)d_in[13];
    const float* fc2_w   = (const float*)d_in[14];
    const float* fc2_b   = (const float*)d_in[15];
    float* out = (float*)d_out;

    static int s_attr_done = 0;
    if (!s_attr_done) {
        cudaFuncSetAttribute(dil_mma_k, cudaFuncAttributeMaxDynamicSharedMemorySize, DSMB);
        cudaFuncSetAttribute(res_mma_k, cudaFuncAttributeMaxDynamicSharedMemorySize, DSMB);
        cudaFuncSetAttribute(init_x_k, cudaFuncAttributeMaxDynamicSharedMemorySize, 65536);
        s_attr_done = 1;
    }

    prep_dil_k<<<61440, 256>>>(dil_w);
    prep_rs_k <<<46336, 256>>>(res_w, skip_w, fc1_w);
    init_x_k<<<dim3(64, 2, 8), 256, (64 * 81 + 80 * 129) * 4>>>(
        mel, audio, start_w, start_b, mel_w, mel_b);

    for (int l = 0; l < NL; l++) {
        int d = 1 << (l % 10);
        dil_mma_k<<<dim3(64, 2, 8), NTHR, DSMB>>>(dil_b, l, d);
        res_mma_k<<<dim3(64, 2, 6), NTHR, DSMB>>>(res_b, skip_b, l);
    }
    fc1_gemm_k<<<dim3(64, 2, 2), 256>>>(fc1_b);
    fc2_k<<<dim3(32, 2), 256>>>(fc2_w, fc2_b, out);
}